// round 14
// baseline (speedup 1.0000x reference)
#include <cuda_runtime.h>
#include <cuda_fp16.h>
#include <cstdint>

#define M_NODES 100000
#define M_PAD   100096      // 782 * 128
#define DSRC    128
#define DOUT    256
#define KA      256         // g_A cols: [dst | agg] fp16
#define MAX_E   600000

// -------- device scratch --------
__device__ __align__(16) int g_cnt[M_NODES];        // zero at every launch start
__device__ __align__(16) int g_off[M_NODES + 1];
__device__ __align__(16) int g_cur[M_NODES];
__device__ __align__(16) int g_csr[MAX_E];
__device__ __align__(16) __half g_A[(size_t)M_PAD * KA];   // 51.2 MB
__device__ __align__(16) __half g_B[KA * DOUT];            // [ke][o] 128KB

// --------------- launch 0: prepW + histogram (fused) --------------------
__global__ void k_prep(const float* __restrict__ W,
                       const int* __restrict__ ei, int E) {
    int t = blockIdx.x * blockDim.x + threadIdx.x;
    if (t < KA * DOUT) {
        int o  = t & (DOUT - 1);
        int ke = t >> 8;
        g_B[ke * DOUT + o] = __float2half_rn(W[o * 256 + ke]);
    }
    if (t < E) atomicAdd(&g_cnt[ei[E + t]], 1);
}

// --------------- launch 1: scan (self-zeroing, emits g_off[M]) ----------
__global__ __launch_bounds__(1024) void k_scan() {
    __shared__ int warp_sums[32];
    const int tid = threadIdx.x;
    const int CH = (M_NODES + 1023) / 1024;   // 98
    int beg = tid * CH;
    int end = min(beg + CH, M_NODES);
    int s = 0;
    for (int i = beg; i < end; i++) s += g_cnt[i];
    int lane = tid & 31, wid = tid >> 5;
    int v = s;
#pragma unroll
    for (int d = 1; d < 32; d <<= 1) {
        int u = __shfl_up_sync(0xffffffffu, v, d);
        if (lane >= d) v += u;
    }
    if (lane == 31) warp_sums[wid] = v;
    __syncthreads();
    if (wid == 0) {
        int w = warp_sums[lane];
#pragma unroll
        for (int d = 1; d < 32; d <<= 1) {
            int u = __shfl_up_sync(0xffffffffu, w, d);
            if (lane >= d) w += u;
        }
        warp_sums[lane] = w;
    }
    __syncthreads();
    int ex = v - s + (wid ? warp_sums[wid - 1] : 0);
    int run = ex;
    for (int i = beg; i < end; i++) {
        g_off[i] = run;
        g_cur[i] = run;
        run += g_cnt[i];
        g_cnt[i] = 0;              // restore invariant for next replay
    }
    if (tid == 1023) g_off[M_NODES] = run;
}

// --------------- launch 2: CSR fill --------------------------------------
__global__ void k_fill(const int* __restrict__ ei, int E) {
    int t = blockIdx.x * blockDim.x + threadIdx.x;
    if (t >= E) return;
    int s = ei[t];
    int d = ei[E + t];
    int pos = atomicAdd(&g_cur[d], 1);
    g_csr[pos] = s;
}

// --------------- launch 3: gather (profiled slot) ------------------------
__global__ void k_gather(const float* __restrict__ xs,
                         const float* __restrict__ xd) {
    int n = blockIdx.x * (blockDim.x >> 5) + (threadIdx.x >> 5);
    int lane = threadIdx.x & 31;
    if (n >= M_NODES) return;
    int beg = g_off[n];
    int end = g_off[n + 1];
    float4 acc = make_float4(0.f, 0.f, 0.f, 0.f);
    int e = beg;
    for (; e + 1 < end; e += 2) {
        int s0 = g_csr[e], s1 = g_csr[e + 1];
        float4 v0 = ((const float4*)(xs + (size_t)s0 * DSRC))[lane];
        float4 v1 = ((const float4*)(xs + (size_t)s1 * DSRC))[lane];
        acc.x += v0.x + v1.x; acc.y += v0.y + v1.y;
        acc.z += v0.z + v1.z; acc.w += v0.w + v1.w;
    }
    if (e < end) {
        int s0 = g_csr[e];
        float4 v0 = ((const float4*)(xs + (size_t)s0 * DSRC))[lane];
        acc.x += v0.x; acc.y += v0.y; acc.z += v0.z; acc.w += v0.w;
    }
    float inv = 1.0f / (float)max(end - beg, 1);
    acc.x *= inv; acc.y *= inv; acc.z *= inv; acc.w *= inv;
    float4 vd = ((const float4*)(xd + (size_t)n * DSRC))[lane];
    __half* row = g_A + (size_t)n * KA;
    __half2* pd = (__half2*)(row + lane * 4);
    pd[0] = __floats2half2_rn(vd.x, vd.y);
    pd[1] = __floats2half2_rn(vd.z, vd.w);
    __half2* pa = (__half2*)(row + 128 + lane * 4);
    pa[0] = __floats2half2_rn(acc.x, acc.y);
    pa[1] = __floats2half2_rn(acc.z, acc.w);
}

// --------------- launch 4: GEMM (R13 verbatim) ---------------------------
#define BM 128
#define BN 256
#define BK 64
#define NT 512
#define NSTAGE 3
#define NCH (KA / BK)              // 4
#define SA_STAGE (BM * BK)
#define SB_STAGE (BK * BN)
#define SMEM_BYTES (NSTAGE * (SA_STAGE + SB_STAGE) * 2)   // 144KB

__device__ __forceinline__ void cp16(void* smem_dst, const void* gsrc) {
    uint32_t s = (uint32_t)__cvta_generic_to_shared(smem_dst);
    asm volatile("cp.async.cg.shared.global [%0], [%1], 16;" :: "r"(s), "l"(gsrc));
}

__global__ __launch_bounds__(NT) void k_gemm(const float* __restrict__ bias,
                                             float* __restrict__ out) {
    extern __shared__ __align__(16) __half smem[];
    __half* sA = smem;                         // [NSTAGE][128][64]
    __half* sB = smem + NSTAGE * SA_STAGE;     // [NSTAGE][64][256]

    const int tid  = threadIdx.x;
    const int lane = tid & 31;
    const int warp = tid >> 5;
    const int wm   = warp >> 2;
    const int wn   = warp & 3;
    const int m0   = blockIdx.x * BM;

    auto load_stage = [&](int kc, int st) {
        int ka = kc * BK;
        __half* sa = sA + st * SA_STAGE;
#pragma unroll
        for (int i = 0; i < 2; i++) {
            int c = tid + i * NT;
            int rowA = c >> 3, cA = c & 7;
            int ph = cA ^ (rowA & 7);
            cp16(sa + rowA * BK + ph * 8,
                 g_A + (size_t)(m0 + rowA) * KA + ka + cA * 8);
        }
        __half* sb = sB + st * SB_STAGE;
#pragma unroll
        for (int i = 0; i < 4; i++) {
            int c = tid + i * NT;
            int rowB = c >> 5, cB = c & 31;
            int ph = (cB & ~7) | ((cB ^ rowB) & 7);
            cp16(sb + rowB * BN + ph * 8,
                 g_B + (size_t)(ka + rowB) * DOUT + cB * 8);
        }
    };

    float acc[2][8][4];
#pragma unroll
    for (int i = 0; i < 2; i++)
#pragma unroll
        for (int j = 0; j < 8; j++)
#pragma unroll
            for (int k = 0; k < 4; k++) acc[i][j][k] = 0.f;

    load_stage(0, 0);
    asm volatile("cp.async.commit_group;");
    load_stage(1, 1);
    asm volatile("cp.async.commit_group;");

#pragma unroll
    for (int kc = 0; kc < NCH; kc++) {
        asm volatile("cp.async.wait_group 1;");   // stage kc complete
        __syncthreads();                          // all warps done with slot (kc-1)%3
        if (kc + 2 < NCH) load_stage(kc + 2, (kc + 2) % NSTAGE);
        asm volatile("cp.async.commit_group;");   // uniform group accounting

        const __half* sa = sA + (kc % NSTAGE) * SA_STAGE;
        const __half* sb = sB + (kc % NSTAGE) * SB_STAGE;

#pragma unroll
        for (int ks = 0; ks < 4; ks++) {
            uint32_t a[2][4], b[8][2];
#pragma unroll
            for (int mf = 0; mf < 2; mf++) {
                int row = wm * 32 + mf * 16 + (lane & 15);
                int c   = ks * 2 + (lane >> 4);
                int ph  = c ^ (row & 7);
                uint32_t addr = (uint32_t)__cvta_generic_to_shared(
                    sa + row * BK + ph * 8);
                asm volatile("ldmatrix.sync.aligned.m8n8.x4.shared.b16 {%0,%1,%2,%3}, [%4];"
                             : "=r"(a[mf][0]), "=r"(a[mf][1]), "=r"(a[mf][2]), "=r"(a[mf][3])
                             : "r"(addr));
            }
#pragma unroll
            for (int nf = 0; nf < 8; nf++) {
                int row = ks * 16 + (lane & 15);
                int cB  = wn * 8 + nf;
                int ph  = (cB & ~7) | ((cB ^ row) & 7);
                uint32_t addr = (uint32_t)__cvta_generic_to_shared(
                    sb + row * BN + ph * 8);
                asm volatile("ldmatrix.sync.aligned.m8n8.x2.trans.shared.b16 {%0,%1}, [%2];"
                             : "=r"(b[nf][0]), "=r"(b[nf][1]) : "r"(addr));
            }
#pragma unroll
            for (int mf = 0; mf < 2; mf++)
#pragma unroll
                for (int nf = 0; nf < 8; nf++) {
                    asm volatile(
                        "mma.sync.aligned.m16n8k16.row.col.f32.f16.f16.f32 "
                        "{%0,%1,%2,%3},{%4,%5,%6,%7},{%8,%9},{%0,%1,%2,%3};"
                        : "+f"(acc[mf][nf][0]), "+f"(acc[mf][nf][1]),
                          "+f"(acc[mf][nf][2]), "+f"(acc[mf][nf][3])
                        : "r"(a[mf][0]), "r"(a[mf][1]), "r"(a[mf][2]), "r"(a[mf][3]),
                          "r"(b[nf][0]), "r"(b[nf][1]));
                }
        }
    }

    // ---- epilogue: bias + ReLU ----
#pragma unroll
    for (int mf = 0; mf < 2; mf++) {
        int r0 = m0 + wm * 32 + mf * 16 + (lane >> 2);
#pragma unroll
        for (int nf = 0; nf < 8; nf++) {
            int c = wn * 64 + nf * 8 + (lane & 3) * 2;
            float b0 = bias[c], b1 = bias[c + 1];
            if (r0 < M_NODES) {
                out[(size_t)r0 * DOUT + c]     = fmaxf(acc[mf][nf][0] + b0, 0.f);
                out[(size_t)r0 * DOUT + c + 1] = fmaxf(acc[mf][nf][1] + b1, 0.f);
            }
            int r1 = r0 + 8;
            if (r1 < M_NODES) {
                out[(size_t)r1 * DOUT + c]     = fmaxf(acc[mf][nf][2] + b0, 0.f);
                out[(size_t)r1 * DOUT + c + 1] = fmaxf(acc[mf][nf][3] + b1, 0.f);
            }
        }
    }
}

// ---------------------------------------------------------------------
extern "C" void kernel_launch(void* const* d_in, const int* in_sizes, int n_in,
                              void* d_out, int out_size) {
    const float* x_src = (const float*)d_in[0];
    const float* x_dst = (const float*)d_in[1];
    const int*   ei    = (const int*)d_in[2];
    const float* W     = (const float*)d_in[3];
    const float* b     = (const float*)d_in[4];
    float*       out   = (float*)d_out;
    int E = in_sizes[2] / 2;

    cudaFuncSetAttribute(k_gemm, cudaFuncAttributeMaxDynamicSharedMemorySize,
                         SMEM_BYTES);

    k_prep<<<(E + 255) / 256, 256>>>(W, ei, E);                   // 0
    k_scan<<<1, 1024>>>();                                        // 1
    k_fill<<<(E + 255) / 256, 256>>>(ei, E);                      // 2
    k_gather<<<(M_NODES * 32 + 255) / 256, 256>>>(x_src, x_dst);  // 3 (profiled)
    k_gemm<<<M_PAD / BM, NT, SMEM_BYTES>>>(b, out);               // 4
}

// round 15
// speedup vs baseline: 2.3139x; 2.3139x over previous
#include <cuda_runtime.h>
#include <cuda_fp16.h>
#include <cstdint>

#define M_NODES 100000
#define M_PAD   100096      // 782 * 128
#define DSRC    128
#define DOUT    256
#define KA      256         // g_A cols: [dst | agg] fp16
#define MAX_E   600000
#define NBLK    98          // scan blocks: ceil(100000/1024)

// -------- device scratch --------
__device__ __align__(16) int g_cnt[M_NODES];
__device__ __align__(16) int g_off[M_NODES];
__device__ __align__(16) int g_cur[M_NODES];
__device__ __align__(16) int g_csr[MAX_E];
__device__ __align__(16) int g_bsum[NBLK];
__device__ __align__(16) int g_boff[NBLK];
__device__ __align__(16) __half g_A[(size_t)M_PAD * KA];   // 51.2 MB
__device__ __align__(16) __half g_B[KA * DOUT];            // [ke][o] 128KB

// ------------------------- CSR build (R13 verbatim) --------------------
__global__ void k_zero() {
    int i = blockIdx.x * blockDim.x + threadIdx.x;
    if (i < M_NODES) g_cnt[i] = 0;
}

__global__ void k_hist(const int* __restrict__ ei, int E) {
    int t = blockIdx.x * blockDim.x + threadIdx.x;
    if (t >= E) return;
    atomicAdd(&g_cnt[ei[E + t]], 1);
}

// ---- scan phase 1: per-block sums (98 blocks x 1024) ----
__global__ __launch_bounds__(1024) void k_scan1() {
    __shared__ int ws[32];
    int t = threadIdx.x;
    int i = blockIdx.x * 1024 + t;
    int v = (i < M_NODES) ? g_cnt[i] : 0;
    int lane = t & 31, wid = t >> 5;
#pragma unroll
    for (int d = 16; d > 0; d >>= 1) v += __shfl_down_sync(0xffffffffu, v, d);
    if (lane == 0) ws[wid] = v;
    __syncthreads();
    if (wid == 0) {
        int w = ws[lane];
#pragma unroll
        for (int d = 16; d > 0; d >>= 1) w += __shfl_down_sync(0xffffffffu, w, d);
        if (lane == 0) g_bsum[blockIdx.x] = w;
    }
}

// ---- scan phase 2: exclusive scan of 98 block sums (1 block, 128 thr) ----
__global__ __launch_bounds__(128) void k_scan2() {
    __shared__ int ws[4];
    int t = threadIdx.x;
    int v = (t < NBLK) ? g_bsum[t] : 0;
    int lane = t & 31, wid = t >> 5;
    int inc = v;
#pragma unroll
    for (int d = 1; d < 32; d <<= 1) {
        int u = __shfl_up_sync(0xffffffffu, inc, d);
        if (lane >= d) inc += u;
    }
    if (lane == 31) ws[wid] = inc;
    __syncthreads();
    int base = 0;
    for (int w = 0; w < 4; w++) {
        if (w < wid) base += ws[w];
    }
    if (t < NBLK) g_boff[t] = base + inc - v;   // exclusive prefix
}

// ---- scan phase 3: block-local exclusive scan + base (98 blocks) ----
__global__ __launch_bounds__(1024) void k_scan3() {
    __shared__ int ws[32];
    int t = threadIdx.x;
    int i = blockIdx.x * 1024 + t;
    int v = (i < M_NODES) ? g_cnt[i] : 0;
    int lane = t & 31, wid = t >> 5;
    int inc = v;
#pragma unroll
    for (int d = 1; d < 32; d <<= 1) {
        int u = __shfl_up_sync(0xffffffffu, inc, d);
        if (lane >= d) inc += u;
    }
    if (lane == 31) ws[wid] = inc;
    __syncthreads();
    if (wid == 0) {
        int w = ws[lane];
#pragma unroll
        for (int d = 1; d < 32; d <<= 1) {
            int u = __shfl_up_sync(0xffffffffu, w, d);
            if (lane >= d) w += u;
        }
        ws[lane] = w;
    }
    __syncthreads();
    int ex = inc - v + (wid ? ws[wid - 1] : 0);
    if (i < M_NODES) {
        int off = g_boff[blockIdx.x] + ex;
        g_off[i] = off;
        g_cur[i] = off;
    }
}

__global__ void k_fill(const int* __restrict__ ei, int E) {
    int t = blockIdx.x * blockDim.x + threadIdx.x;
    if (t >= E) return;
    int s = ei[t];
    int d = ei[E + t];
    int pos = atomicAdd(&g_cur[d], 1);
    g_csr[pos] = s;
}

// W [256 out, 256 in] fp32 -> g_B [256 ke][256 o] fp16 (R13 verbatim)
__global__ void k_prepW(const float* __restrict__ W) {
    int t = blockIdx.x * blockDim.x + threadIdx.x;
    if (t >= KA * DOUT) return;
    int o  = t & (DOUT - 1);
    int ke = t >> 8;
    g_B[ke * DOUT + o] = __float2half_rn(W[o * 256 + ke]);
}

// ------------------------- gather (R13 verbatim) ------------------------
__global__ void k_gather(const float* __restrict__ xs,
                         const float* __restrict__ xd) {
    int n = blockIdx.x * (blockDim.x >> 5) + (threadIdx.x >> 5);
    int lane = threadIdx.x & 31;
    if (n >= M_NODES) return;
    int beg = g_off[n];
    int end = beg + g_cnt[n];
    float4 acc = make_float4(0.f, 0.f, 0.f, 0.f);
    int e = beg;
    for (; e + 1 < end; e += 2) {
        int s0 = g_csr[e], s1 = g_csr[e + 1];
        float4 v0 = ((const float4*)(xs + (size_t)s0 * DSRC))[lane];
        float4 v1 = ((const float4*)(xs + (size_t)s1 * DSRC))[lane];
        acc.x += v0.x + v1.x; acc.y += v0.y + v1.y;
        acc.z += v0.z + v1.z; acc.w += v0.w + v1.w;
    }
    if (e < end) {
        int s0 = g_csr[e];
        float4 v0 = ((const float4*)(xs + (size_t)s0 * DSRC))[lane];
        acc.x += v0.x; acc.y += v0.y; acc.z += v0.z; acc.w += v0.w;
    }
    float inv = 1.0f / (float)max(end - beg, 1);
    acc.x *= inv; acc.y *= inv; acc.z *= inv; acc.w *= inv;
    float4 vd = ((const float4*)(xd + (size_t)n * DSRC))[lane];
    __half* row = g_A + (size_t)n * KA;
    __half2* pd = (__half2*)(row + lane * 4);
    pd[0] = __floats2half2_rn(vd.x, vd.y);
    pd[1] = __floats2half2_rn(vd.z, vd.w);
    __half2* pa = (__half2*)(row + 128 + lane * 4);
    pa[0] = __floats2half2_rn(acc.x, acc.y);
    pa[1] = __floats2half2_rn(acc.z, acc.w);
}

// ------------------------- GEMM (R13 verbatim) --------------------------
#define BM 128
#define BN 256
#define BK 64
#define NT 512
#define NSTAGE 3
#define NCH (KA / BK)              // 4
#define SA_STAGE (BM * BK)
#define SB_STAGE (BK * BN)
#define SMEM_BYTES (NSTAGE * (SA_STAGE + SB_STAGE) * 2)   // 144KB

__device__ __forceinline__ void cp16(void* smem_dst, const void* gsrc) {
    uint32_t s = (uint32_t)__cvta_generic_to_shared(smem_dst);
    asm volatile("cp.async.cg.shared.global [%0], [%1], 16;" :: "r"(s), "l"(gsrc));
}

__global__ __launch_bounds__(NT) void k_gemm(const float* __restrict__ bias,
                                             float* __restrict__ out) {
    extern __shared__ __align__(16) __half smem[];
    __half* sA = smem;
    __half* sB = smem + NSTAGE * SA_STAGE;

    const int tid  = threadIdx.x;
    const int lane = tid & 31;
    const int warp = tid >> 5;
    const int wm   = warp >> 2;
    const int wn   = warp & 3;
    const int m0   = blockIdx.x * BM;

    auto load_stage = [&](int kc, int st) {
        int ka = kc * BK;
        __half* sa = sA + st * SA_STAGE;
#pragma unroll
        for (int i = 0; i < 2; i++) {
            int c = tid + i * NT;
            int rowA = c >> 3, cA = c & 7;
            int ph = cA ^ (rowA & 7);
            cp16(sa + rowA * BK + ph * 8,
                 g_A + (size_t)(m0 + rowA) * KA + ka + cA * 8);
        }
        __half* sb = sB + st * SB_STAGE;
#pragma unroll
        for (int i = 0; i < 4; i++) {
            int c = tid + i * NT;
            int rowB = c >> 5, cB = c & 31;
            int ph = (cB & ~7) | ((cB ^ rowB) & 7);
            cp16(sb + rowB * BN + ph * 8,
                 g_B + (size_t)(ka + rowB) * DOUT + cB * 8);
        }
    };

    float acc[2][8][4];
#pragma unroll
    for (int i = 0; i < 2; i++)
#pragma unroll
        for (int j = 0; j < 8; j++)
#pragma unroll
            for (int k = 0; k < 4; k++) acc[i][j][k] = 0.f;

    load_stage(0, 0);
    asm volatile("cp.async.commit_group;");
    load_stage(1, 1);
    asm volatile("cp.async.commit_group;");

#pragma unroll
    for (int kc = 0; kc < NCH; kc++) {
        asm volatile("cp.async.wait_group 1;");
        __syncthreads();
        if (kc + 2 < NCH) load_stage(kc + 2, (kc + 2) % NSTAGE);
        asm volatile("cp.async.commit_group;");

        const __half* sa = sA + (kc % NSTAGE) * SA_STAGE;
        const __half* sb = sB + (kc % NSTAGE) * SB_STAGE;

#pragma unroll
        for (int ks = 0; ks < 4; ks++) {
            uint32_t a[2][4], b[8][2];
#pragma unroll
            for (int mf = 0; mf < 2; mf++) {
                int row = wm * 32 + mf * 16 + (lane & 15);
                int c   = ks * 2 + (lane >> 4);
                int ph  = c ^ (row & 7);
                uint32_t addr = (uint32_t)__cvta_generic_to_shared(
                    sa + row * BK + ph * 8);
                asm volatile("ldmatrix.sync.aligned.m8n8.x4.shared.b16 {%0,%1,%2,%3}, [%4];"
                             : "=r"(a[mf][0]), "=r"(a[mf][1]), "=r"(a[mf][2]), "=r"(a[mf][3])
                             : "r"(addr));
            }
#pragma unroll
            for (int nf = 0; nf < 8; nf++) {
                int row = ks * 16 + (lane & 15);
                int cB  = wn * 8 + nf;
                int ph  = (cB & ~7) | ((cB ^ row) & 7);
                uint32_t addr = (uint32_t)__cvta_generic_to_shared(
                    sb + row * BN + ph * 8);
                asm volatile("ldmatrix.sync.aligned.m8n8.x2.trans.shared.b16 {%0,%1}, [%2];"
                             : "=r"(b[nf][0]), "=r"(b[nf][1]) : "r"(addr));
            }
#pragma unroll
            for (int mf = 0; mf < 2; mf++)
#pragma unroll
                for (int nf = 0; nf < 8; nf++) {
                    asm volatile(
                        "mma.sync.aligned.m16n8k16.row.col.f32.f16.f16.f32 "
                        "{%0,%1,%2,%3},{%4,%5,%6,%7},{%8,%9},{%0,%1,%2,%3};"
                        : "+f"(acc[mf][nf][0]), "+f"(acc[mf][nf][1]),
                          "+f"(acc[mf][nf][2]), "+f"(acc[mf][nf][3])
                        : "r"(a[mf][0]), "r"(a[mf][1]), "r"(a[mf][2]), "r"(a[mf][3]),
                          "r"(b[nf][0]), "r"(b[nf][1]));
                }
        }
    }

#pragma unroll
    for (int mf = 0; mf < 2; mf++) {
        int r0 = m0 + wm * 32 + mf * 16 + (lane >> 2);
#pragma unroll
        for (int nf = 0; nf < 8; nf++) {
            int c = wn * 64 + nf * 8 + (lane & 3) * 2;
            float b0 = bias[c], b1 = bias[c + 1];
            if (r0 < M_NODES) {
                out[(size_t)r0 * DOUT + c]     = fmaxf(acc[mf][nf][0] + b0, 0.f);
                out[(size_t)r0 * DOUT + c + 1] = fmaxf(acc[mf][nf][1] + b1, 0.f);
            }
            int r1 = r0 + 8;
            if (r1 < M_NODES) {
                out[(size_t)r1 * DOUT + c]     = fmaxf(acc[mf][nf][2] + b0, 0.f);
                out[(size_t)r1 * DOUT + c + 1] = fmaxf(acc[mf][nf][3] + b1, 0.f);
            }
        }
    }
}

// ---------------------------------------------------------------------
extern "C" void kernel_launch(void* const* d_in, const int* in_sizes, int n_in,
                              void* d_out, int out_size) {
    const float* x_src = (const float*)d_in[0];
    const float* x_dst = (const float*)d_in[1];
    const int*   ei    = (const int*)d_in[2];
    const float* W     = (const float*)d_in[3];
    const float* b     = (const float*)d_in[4];
    float*       out   = (float*)d_out;
    int E = in_sizes[2] / 2;

    cudaFuncSetAttribute(k_gemm, cudaFuncAttributeMaxDynamicSharedMemorySize,
                         SMEM_BYTES);

    k_zero<<<(M_NODES + 255) / 256, 256>>>();
    k_hist<<<(E + 255) / 256, 256>>>(ei, E);
    k_scan1<<<NBLK, 1024>>>();
    k_scan2<<<1, 128>>>();
    k_scan3<<<NBLK, 1024>>>();
    k_fill<<<(E + 255) / 256, 256>>>(ei, E);
    k_prepW<<<(KA * DOUT + 255) / 256, 256>>>(W);
    k_gather<<<(M_NODES * 32 + 255) / 256, 256>>>(x_src, x_dst);
    k_gemm<<<M_PAD / BM, NT, SMEM_BYTES>>>(b, out);
}

// round 16
// speedup vs baseline: 2.4799x; 1.0717x over previous
#include <cuda_runtime.h>
#include <cuda_fp16.h>
#include <cstdint>

#define M_NODES 100000
#define M_PAD   100096      // 782 * 128
#define DSRC    128
#define DOUT    256
#define KA      256         // g_A cols: [dst | agg] fp16
#define MAX_E   600000
#define NBLK    98          // scan blocks: ceil(100000/1024)

// -------- device scratch --------
__device__ __align__(16) int g_cnt[M_NODES];
__device__ __align__(16) int g_off[M_NODES];
__device__ __align__(16) int g_cur[M_NODES];
__device__ __align__(16) int g_csr[MAX_E];
__device__ __align__(16) int g_bsum[NBLK];
__device__ __align__(16) int g_boff[NBLK];
__device__ __align__(16) __half g_A[(size_t)M_PAD * KA];   // 51.2 MB
__device__ __align__(16) __half g_B[KA * DOUT];            // [ke][o] 128KB

// ------------------------- CSR build -----------------------------------
__global__ void k_zero() {
    int i = blockIdx.x * blockDim.x + threadIdx.x;
    if (i < M_NODES) g_cnt[i] = 0;
}

__global__ void k_hist(const int* __restrict__ ei, int E) {
    int t = blockIdx.x * blockDim.x + threadIdx.x;
    if (t >= E) return;
    atomicAdd(&g_cnt[ei[E + t]], 1);
}

// ---- scan phase 1: per-block sums (98 blocks x 1024) ----
__global__ __launch_bounds__(1024) void k_scan1() {
    __shared__ int ws[32];
    int t = threadIdx.x;
    int i = blockIdx.x * 1024 + t;
    int v = (i < M_NODES) ? g_cnt[i] : 0;
    int lane = t & 31, wid = t >> 5;
#pragma unroll
    for (int d = 16; d > 0; d >>= 1) v += __shfl_down_sync(0xffffffffu, v, d);
    if (lane == 0) ws[wid] = v;
    __syncthreads();
    if (wid == 0) {
        int w = ws[lane];
#pragma unroll
        for (int d = 16; d > 0; d >>= 1) w += __shfl_down_sync(0xffffffffu, w, d);
        if (lane == 0) g_bsum[blockIdx.x] = w;
    }
}

// ---- scan phase 2: exclusive scan of 98 block sums ----
__global__ __launch_bounds__(128) void k_scan2() {
    __shared__ int ws[4];
    int t = threadIdx.x;
    int v = (t < NBLK) ? g_bsum[t] : 0;
    int lane = t & 31, wid = t >> 5;
    int inc = v;
#pragma unroll
    for (int d = 1; d < 32; d <<= 1) {
        int u = __shfl_up_sync(0xffffffffu, inc, d);
        if (lane >= d) inc += u;
    }
    if (lane == 31) ws[wid] = inc;
    __syncthreads();
    int base = 0;
    for (int w = 0; w < 4; w++) {
        if (w < wid) base += ws[w];
    }
    if (t < NBLK) g_boff[t] = base + inc - v;   // exclusive prefix
}

// ---- scan phase 3: block-local exclusive scan + base ----
__global__ __launch_bounds__(1024) void k_scan3() {
    __shared__ int ws[32];
    int t = threadIdx.x;
    int i = blockIdx.x * 1024 + t;
    int v = (i < M_NODES) ? g_cnt[i] : 0;
    int lane = t & 31, wid = t >> 5;
    int inc = v;
#pragma unroll
    for (int d = 1; d < 32; d <<= 1) {
        int u = __shfl_up_sync(0xffffffffu, inc, d);
        if (lane >= d) inc += u;
    }
    if (lane == 31) ws[wid] = inc;
    __syncthreads();
    if (wid == 0) {
        int w = ws[lane];
#pragma unroll
        for (int d = 1; d < 32; d <<= 1) {
            int u = __shfl_up_sync(0xffffffffu, w, d);
            if (lane >= d) w += u;
        }
        ws[lane] = w;
    }
    __syncthreads();
    int ex = inc - v + (wid ? ws[wid - 1] : 0);
    if (i < M_NODES) {
        int off = g_boff[blockIdx.x] + ex;
        g_off[i] = off;
        g_cur[i] = off;
    }
}

__global__ void k_fill(const int* __restrict__ ei, int E) {
    int t = blockIdx.x * blockDim.x + threadIdx.x;
    if (t >= E) return;
    int s = ei[t];
    int d = ei[E + t];
    int pos = atomicAdd(&g_cur[d], 1);
    g_csr[pos] = s;
}

// W [256 out, 256 in] fp32 -> g_B [256 ke][256 o] fp16
__global__ void k_prepW(const float* __restrict__ W) {
    int t = blockIdx.x * blockDim.x + threadIdx.x;
    if (t >= KA * DOUT) return;
    int o  = t & (DOUT - 1);
    int ke = t >> 8;
    g_B[ke * DOUT + o] = __float2half_rn(W[o * 256 + ke]);
}

// ------------------------- gather (R13 verbatim) ------------------------
__global__ void k_gather(const float* __restrict__ xs,
                         const float* __restrict__ xd) {
    int n = blockIdx.x * (blockDim.x >> 5) + (threadIdx.x >> 5);
    int lane = threadIdx.x & 31;
    if (n >= M_NODES) return;
    int beg = g_off[n];
    int end = beg + g_cnt[n];
    float4 acc = make_float4(0.f, 0.f, 0.f, 0.f);
    int e = beg;
    for (; e + 1 < end; e += 2) {
        int s0 = g_csr[e], s1 = g_csr[e + 1];
        float4 v0 = ((const float4*)(xs + (size_t)s0 * DSRC))[lane];
        float4 v1 = ((const float4*)(xs + (size_t)s1 * DSRC))[lane];
        acc.x += v0.x + v1.x; acc.y += v0.y + v1.y;
        acc.z += v0.z + v1.z; acc.w += v0.w + v1.w;
    }
    if (e < end) {
        int s0 = g_csr[e];
        float4 v0 = ((const float4*)(xs + (size_t)s0 * DSRC))[lane];
        acc.x += v0.x; acc.y += v0.y; acc.z += v0.z; acc.w += v0.w;
    }
    float inv = 1.0f / (float)max(end - beg, 1);
    acc.x *= inv; acc.y *= inv; acc.z *= inv; acc.w *= inv;
    float4 vd = ((const float4*)(xd + (size_t)n * DSRC))[lane];
    __half* row = g_A + (size_t)n * KA;
    __half2* pd = (__half2*)(row + lane * 4);
    pd[0] = __floats2half2_rn(vd.x, vd.y);
    pd[1] = __floats2half2_rn(vd.z, vd.w);
    __half2* pa = (__half2*)(row + 128 + lane * 4);
    pa[0] = __floats2half2_rn(acc.x, acc.y);
    pa[1] = __floats2half2_rn(acc.z, acc.w);
}

// ---------- GEMM: BN=128, NT=256, 2 CTAs/SM, single-sync pipeline -------
#define BM 128
#define BN 128
#define BK 64
#define NT 256
#define NSTAGE 3
#define NCH (KA / BK)              // 4
#define SA_STAGE (BM * BK)         // 16KB
#define SB_STAGE (BK * BN)         // 16KB
#define SMEM_BYTES (NSTAGE * (SA_STAGE + SB_STAGE) * 2)   // 96KB

__device__ __forceinline__ void cp16(void* smem_dst, const void* gsrc) {
    uint32_t s = (uint32_t)__cvta_generic_to_shared(smem_dst);
    asm volatile("cp.async.cg.shared.global [%0], [%1], 16;" :: "r"(s), "l"(gsrc));
}

__global__ __launch_bounds__(NT, 2) void k_gemm(const float* __restrict__ bias,
                                                float* __restrict__ out) {
    extern __shared__ __align__(16) __half smem[];
    __half* sA = smem;                         // [NSTAGE][128][64]
    __half* sB = smem + NSTAGE * SA_STAGE;     // [NSTAGE][64][128]

    const int tid  = threadIdx.x;
    const int lane = tid & 31;
    const int warp = tid >> 5;       // 0..7
    const int wm   = warp >> 1;      // 0..3 -> 32 rows
    const int wn   = warp & 1;       // 0..1 -> 64 cols
    const int m0   = blockIdx.x * BM;
    const int n0   = blockIdx.y * BN;

    auto load_stage = [&](int kc, int st) {
        int ka = kc * BK;
        __half* sa = sA + st * SA_STAGE;
#pragma unroll
        for (int i = 0; i < 4; i++) {          // A: 1024 16B chunks / 256 thr
            int c = tid + i * NT;
            int rowA = c >> 3, cA = c & 7;
            int ph = cA ^ (rowA & 7);
            cp16(sa + rowA * BK + ph * 8,
                 g_A + (size_t)(m0 + rowA) * KA + ka + cA * 8);
        }
        __half* sb = sB + st * SB_STAGE;
#pragma unroll
        for (int i = 0; i < 4; i++) {          // B: 1024 16B chunks / 256 thr
            int c = tid + i * NT;
            int rowB = c >> 4, cB = c & 15;
            int ph = (cB & ~7) | ((cB ^ rowB) & 7);
            cp16(sb + rowB * BN + ph * 8,
                 g_B + (size_t)(ka + rowB) * DOUT + n0 + cB * 8);
        }
    };

    float acc[2][8][4];
#pragma unroll
    for (int i = 0; i < 2; i++)
#pragma unroll
        for (int j = 0; j < 8; j++)
#pragma unroll
            for (int k = 0; k < 4; k++) acc[i][j][k] = 0.f;

    load_stage(0, 0);
    asm volatile("cp.async.commit_group;");
    load_stage(1, 1);
    asm volatile("cp.async.commit_group;");

#pragma unroll
    for (int kc = 0; kc < NCH; kc++) {
        asm volatile("cp.async.wait_group 1;");   // stage kc complete
        __syncthreads();                          // done reading slot (kc-1)%3
        if (kc + 2 < NCH) load_stage(kc + 2, (kc + 2) % NSTAGE);
        asm volatile("cp.async.commit_group;");

        const __half* sa = sA + (kc % NSTAGE) * SA_STAGE;
        const __half* sb = sB + (kc % NSTAGE) * SB_STAGE;

#pragma unroll
        for (int ks = 0; ks < 4; ks++) {
            uint32_t a[2][4], b[8][2];
#pragma unroll
            for (int mf = 0; mf < 2; mf++) {
                int row = wm * 32 + mf * 16 + (lane & 15);
                int c   = ks * 2 + (lane >> 4);
                int ph  = c ^ (row & 7);
                uint32_t addr = (uint32_t)__cvta_generic_to_shared(
                    sa + row * BK + ph * 8);
                asm volatile("ldmatrix.sync.aligned.m8n8.x4.shared.b16 {%0,%1,%2,%3}, [%4];"
                             : "=r"(a[mf][0]), "=r"(a[mf][1]), "=r"(a[mf][2]), "=r"(a[mf][3])
                             : "r"(addr));
            }
#pragma unroll
            for (int nf = 0; nf < 8; nf++) {
                int row = ks * 16 + (lane & 15);
                int cB  = wn * 8 + nf;
                int ph  = (cB & ~7) | ((cB ^ row) & 7);
                uint32_t addr = (uint32_t)__cvta_generic_to_shared(
                    sb + row * BN + ph * 8);
                asm volatile("ldmatrix.sync.aligned.m8n8.x2.trans.shared.b16 {%0,%1}, [%2];"
                             : "=r"(b[nf][0]), "=r"(b[nf][1]) : "r"(addr));
            }
#pragma unroll
            for (int mf = 0; mf < 2; mf++)
#pragma unroll
                for (int nf = 0; nf < 8; nf++) {
                    asm volatile(
                        "mma.sync.aligned.m16n8k16.row.col.f32.f16.f16.f32 "
                        "{%0,%1,%2,%3},{%4,%5,%6,%7},{%8,%9},{%0,%1,%2,%3};"
                        : "+f"(acc[mf][nf][0]), "+f"(acc[mf][nf][1]),
                          "+f"(acc[mf][nf][2]), "+f"(acc[mf][nf][3])
                        : "r"(a[mf][0]), "r"(a[mf][1]), "r"(a[mf][2]), "r"(a[mf][3]),
                          "r"(b[nf][0]), "r"(b[nf][1]));
                }
        }
    }

    // ---- epilogue: bias + ReLU ----
#pragma unroll
    for (int mf = 0; mf < 2; mf++) {
        int r0 = m0 + wm * 32 + mf * 16 + (lane >> 2);
#pragma unroll
        for (int nf = 0; nf < 8; nf++) {
            int c = n0 + wn * 64 + nf * 8 + (lane & 3) * 2;
            float b0 = bias[c], b1 = bias[c + 1];
            if (r0 < M_NODES) {
                out[(size_t)r0 * DOUT + c]     = fmaxf(acc[mf][nf][0] + b0, 0.f);
                out[(size_t)r0 * DOUT + c + 1] = fmaxf(acc[mf][nf][1] + b1, 0.f);
            }
            int r1 = r0 + 8;
            if (r1 < M_NODES) {
                out[(size_t)r1 * DOUT + c]     = fmaxf(acc[mf][nf][2] + b0, 0.f);
                out[(size_t)r1 * DOUT + c + 1] = fmaxf(acc[mf][nf][3] + b1, 0.f);
            }
        }
    }
}

// ---------------------------------------------------------------------
extern "C" void kernel_launch(void* const* d_in, const int* in_sizes, int n_in,
                              void* d_out, int out_size) {
    const float* x_src = (const float*)d_in[0];
    const float* x_dst = (const float*)d_in[1];
    const int*   ei    = (const int*)d_in[2];
    const float* W     = (const float*)d_in[3];
    const float* b     = (const float*)d_in[4];
    float*       out   = (float*)d_out;
    int E = in_sizes[2] / 2;

    cudaFuncSetAttribute(k_gemm, cudaFuncAttributeMaxDynamicSharedMemorySize,
                         SMEM_BYTES);

    k_zero<<<(M_NODES + 255) / 256, 256>>>();
    k_hist<<<(E + 255) / 256, 256>>>(ei, E);
    k_scan1<<<NBLK, 1024>>>();
    k_scan2<<<1, 128>>>();
    k_scan3<<<NBLK, 1024>>>();
    k_fill<<<(E + 255) / 256, 256>>>(ei, E);
    k_prepW<<<(KA * DOUT + 255) / 256, 256>>>(W);
    k_gather<<<(M_NODES * 32 + 255) / 256, 256>>>(x_src, x_dst);
    dim3 grid(M_PAD / BM, DOUT / BN);
    k_gemm<<<grid, NT, SMEM_BYTES>>>(b, out);
}

// round 17
// speedup vs baseline: 2.5351x; 1.0222x over previous
#include <cuda_runtime.h>
#include <cuda_fp16.h>
#include <cstdint>

#define M_NODES 100000
#define M_PAD   100096      // 782 * 128
#define DSRC    128
#define DOUT    256
#define KA      256         // g_A cols: [dst | agg] fp16
#define MAX_E   600000
#define NBLK    98          // scan blocks: ceil(100000/1024)

// -------- device scratch --------
__device__ __align__(16) int g_cnt[M_NODES];
__device__ __align__(16) int g_off[M_NODES];
__device__ __align__(16) int g_cur[M_NODES];
__device__ __align__(16) int g_csr[MAX_E];
__device__ __align__(16) int g_bsum[NBLK];
__device__ __align__(16) __half g_A[(size_t)M_PAD * KA];   // 51.2 MB
__device__ __align__(16) __half g_B[KA * DOUT];            // [ke][o] 128KB

// ---------- launch 0: zero counters + prepW (independent, fused) --------
__global__ void k_init(const float* __restrict__ W) {
    int t = blockIdx.x * blockDim.x + threadIdx.x;
    if (t < M_NODES) g_cnt[t] = 0;
    if (t < KA * DOUT) {
        int o  = t & (DOUT - 1);
        int ke = t >> 8;
        g_B[ke * DOUT + o] = __float2half_rn(W[o * 256 + ke]);
    }
}

// ---------- launch 1: histogram ------------------------------------------
__global__ void k_hist(const int* __restrict__ ei, int E) {
    int t = blockIdx.x * blockDim.x + threadIdx.x;
    if (t >= E) return;
    atomicAdd(&g_cnt[ei[E + t]], 1);
}

// ---------- launch 2: per-block sums (98 blocks x 1024) ------------------
__global__ __launch_bounds__(1024) void k_scan1() {
    __shared__ int ws[32];
    int t = threadIdx.x;
    int i = blockIdx.x * 1024 + t;
    int v = (i < M_NODES) ? g_cnt[i] : 0;
    int lane = t & 31, wid = t >> 5;
#pragma unroll
    for (int d = 16; d > 0; d >>= 1) v += __shfl_down_sync(0xffffffffu, v, d);
    if (lane == 0) ws[wid] = v;
    __syncthreads();
    if (wid == 0) {
        int w = ws[lane];
#pragma unroll
        for (int d = 16; d > 0; d >>= 1) w += __shfl_down_sync(0xffffffffu, w, d);
        if (lane == 0) g_bsum[blockIdx.x] = w;
    }
}

// ---------- launch 3: local scan + inline base from bsums ----------------
__global__ __launch_bounds__(1024) void k_scan3() {
    __shared__ int ws[32];
    __shared__ int s_base;
    int t = threadIdx.x;
    int i = blockIdx.x * 1024 + t;
    int v = (i < M_NODES) ? g_cnt[i] : 0;
    int lane = t & 31, wid = t >> 5;

    // warp 0: block base = sum of g_bsum[0..bid)
    if (wid == 0) {
        int b = 0;
        for (int j = lane; j < blockIdx.x; j += 32) b += g_bsum[j];
#pragma unroll
        for (int d = 16; d > 0; d >>= 1) b += __shfl_down_sync(0xffffffffu, b, d);
        if (lane == 0) s_base = b;
    }

    // local inclusive scan
    int inc = v;
#pragma unroll
    for (int d = 1; d < 32; d <<= 1) {
        int u = __shfl_up_sync(0xffffffffu, inc, d);
        if (lane >= d) inc += u;
    }
    if (lane == 31) ws[wid] = inc;
    __syncthreads();
    if (wid == 0) {
        int w = ws[lane];
#pragma unroll
        for (int d = 1; d < 32; d <<= 1) {
            int u = __shfl_up_sync(0xffffffffu, w, d);
            if (lane >= d) w += u;
        }
        ws[lane] = w;
    }
    __syncthreads();
    int ex = inc - v + (wid ? ws[wid - 1] : 0);
    if (i < M_NODES) {
        int off = s_base + ex;
        g_off[i] = off;
        g_cur[i] = off;
    }
}

// ---------- launch 4: CSR fill --------------------------------------------
__global__ void k_fill(const int* __restrict__ ei, int E) {
    int t = blockIdx.x * blockDim.x + threadIdx.x;
    if (t >= E) return;
    int s = ei[t];
    int d = ei[E + t];
    int pos = atomicAdd(&g_cur[d], 1);
    g_csr[pos] = s;
}

// ---------- launch 5: gather (streaming g_A stores) ------------------------
__global__ void k_gather(const float* __restrict__ xs,
                         const float* __restrict__ xd) {
    int n = blockIdx.x * (blockDim.x >> 5) + (threadIdx.x >> 5);
    int lane = threadIdx.x & 31;
    if (n >= M_NODES) return;
    int beg = g_off[n];
    int end = beg + g_cnt[n];
    float4 acc = make_float4(0.f, 0.f, 0.f, 0.f);
    int e = beg;
    for (; e + 1 < end; e += 2) {
        int s0 = g_csr[e], s1 = g_csr[e + 1];
        float4 v0 = ((const float4*)(xs + (size_t)s0 * DSRC))[lane];
        float4 v1 = ((const float4*)(xs + (size_t)s1 * DSRC))[lane];
        acc.x += v0.x + v1.x; acc.y += v0.y + v1.y;
        acc.z += v0.z + v1.z; acc.w += v0.w + v1.w;
    }
    if (e < end) {
        int s0 = g_csr[e];
        float4 v0 = ((const float4*)(xs + (size_t)s0 * DSRC))[lane];
        acc.x += v0.x; acc.y += v0.y; acc.z += v0.z; acc.w += v0.w;
    }
    float inv = 1.0f / (float)max(end - beg, 1);
    acc.x *= inv; acc.y *= inv; acc.z *= inv; acc.w *= inv;
    float4 vd = ((const float4*)(xd + (size_t)n * DSRC))[lane];

    __half2 h0 = __floats2half2_rn(vd.x, vd.y);
    __half2 h1 = __floats2half2_rn(vd.z, vd.w);
    __half2 h2 = __floats2half2_rn(acc.x, acc.y);
    __half2 h3 = __floats2half2_rn(acc.z, acc.w);
    uint32_t u0 = *(uint32_t*)&h0, u1 = *(uint32_t*)&h1;
    uint32_t u2 = *(uint32_t*)&h2, u3 = *(uint32_t*)&h3;
    __half* row = g_A + (size_t)n * KA;
    // evict-first streaming stores: keep x_src resident in L2
    asm volatile("st.global.cs.v2.b32 [%0], {%1,%2};"
                 :: "l"(row + lane * 4), "r"(u0), "r"(u1) : "memory");
    asm volatile("st.global.cs.v2.b32 [%0], {%1,%2};"
                 :: "l"(row + 128 + lane * 4), "r"(u2), "r"(u3) : "memory");
}

// ---------- launch 6: GEMM (R16 verbatim: 2 CTAs/SM) -----------------------
#define BM 128
#define BN 128
#define BK 64
#define NT 256
#define NSTAGE 3
#define NCH (KA / BK)              // 4
#define SA_STAGE (BM * BK)         // 16KB
#define SB_STAGE (BK * BN)         // 16KB
#define SMEM_BYTES (NSTAGE * (SA_STAGE + SB_STAGE) * 2)   // 96KB

__device__ __forceinline__ void cp16(void* smem_dst, const void* gsrc) {
    uint32_t s = (uint32_t)__cvta_generic_to_shared(smem_dst);
    asm volatile("cp.async.cg.shared.global [%0], [%1], 16;" :: "r"(s), "l"(gsrc));
}

__global__ __launch_bounds__(NT, 2) void k_gemm(const float* __restrict__ bias,
                                                float* __restrict__ out) {
    extern __shared__ __align__(16) __half smem[];
    __half* sA = smem;                         // [NSTAGE][128][64]
    __half* sB = smem + NSTAGE * SA_STAGE;     // [NSTAGE][64][128]

    const int tid  = threadIdx.x;
    const int lane = tid & 31;
    const int warp = tid >> 5;       // 0..7
    const int wm   = warp >> 1;      // 0..3 -> 32 rows
    const int wn   = warp & 1;       // 0..1 -> 64 cols
    const int m0   = blockIdx.x * BM;
    const int n0   = blockIdx.y * BN;

    auto load_stage = [&](int kc, int st) {
        int ka = kc * BK;
        __half* sa = sA + st * SA_STAGE;
#pragma unroll
        for (int i = 0; i < 4; i++) {
            int c = tid + i * NT;
            int rowA = c >> 3, cA = c & 7;
            int ph = cA ^ (rowA & 7);
            cp16(sa + rowA * BK + ph * 8,
                 g_A + (size_t)(m0 + rowA) * KA + ka + cA * 8);
        }
        __half* sb = sB + st * SB_STAGE;
#pragma unroll
        for (int i = 0; i < 4; i++) {
            int c = tid + i * NT;
            int rowB = c >> 4, cB = c & 15;
            int ph = (cB & ~7) | ((cB ^ rowB) & 7);
            cp16(sb + rowB * BN + ph * 8,
                 g_B + (size_t)(ka + rowB) * DOUT + n0 + cB * 8);
        }
    };

    float acc[2][8][4];
#pragma unroll
    for (int i = 0; i < 2; i++)
#pragma unroll
        for (int j = 0; j < 8; j++)
#pragma unroll
            for (int k = 0; k < 4; k++) acc[i][j][k] = 0.f;

    load_stage(0, 0);
    asm volatile("cp.async.commit_group;");
    load_stage(1, 1);
    asm volatile("cp.async.commit_group;");

#pragma unroll
    for (int kc = 0; kc < NCH; kc++) {
        asm volatile("cp.async.wait_group 1;");
        __syncthreads();
        if (kc + 2 < NCH) load_stage(kc + 2, (kc + 2) % NSTAGE);
        asm volatile("cp.async.commit_group;");

        const __half* sa = sA + (kc % NSTAGE) * SA_STAGE;
        const __half* sb = sB + (kc % NSTAGE) * SB_STAGE;

#pragma unroll
        for (int ks = 0; ks < 4; ks++) {
            uint32_t a[2][4], b[8][2];
#pragma unroll
            for (int mf = 0; mf < 2; mf++) {
                int row = wm * 32 + mf * 16 + (lane & 15);
                int c   = ks * 2 + (lane >> 4);
                int ph  = c ^ (row & 7);
                uint32_t addr = (uint32_t)__cvta_generic_to_shared(
                    sa + row * BK + ph * 8);
                asm volatile("ldmatrix.sync.aligned.m8n8.x4.shared.b16 {%0,%1,%2,%3}, [%4];"
                             : "=r"(a[mf][0]), "=r"(a[mf][1]), "=r"(a[mf][2]), "=r"(a[mf][3])
                             : "r"(addr));
            }
#pragma unroll
            for (int nf = 0; nf < 8; nf++) {
                int row = ks * 16 + (lane & 15);
                int cB  = wn * 8 + nf;
                int ph  = (cB & ~7) | ((cB ^ row) & 7);
                uint32_t addr = (uint32_t)__cvta_generic_to_shared(
                    sb + row * BN + ph * 8);
                asm volatile("ldmatrix.sync.aligned.m8n8.x2.trans.shared.b16 {%0,%1}, [%2];"
                             : "=r"(b[nf][0]), "=r"(b[nf][1]) : "r"(addr));
            }
#pragma unroll
            for (int mf = 0; mf < 2; mf++)
#pragma unroll
                for (int nf = 0; nf < 8; nf++) {
                    asm volatile(
                        "mma.sync.aligned.m16n8k16.row.col.f32.f16.f16.f32 "
                        "{%0,%1,%2,%3},{%4,%5,%6,%7},{%8,%9},{%0,%1,%2,%3};"
                        : "+f"(acc[mf][nf][0]), "+f"(acc[mf][nf][1]),
                          "+f"(acc[mf][nf][2]), "+f"(acc[mf][nf][3])
                        : "r"(a[mf][0]), "r"(a[mf][1]), "r"(a[mf][2]), "r"(a[mf][3]),
                          "r"(b[nf][0]), "r"(b[nf][1]));
                }
        }
    }

#pragma unroll
    for (int mf = 0; mf < 2; mf++) {
        int r0 = m0 + wm * 32 + mf * 16 + (lane >> 2);
#pragma unroll
        for (int nf = 0; nf < 8; nf++) {
            int c = n0 + wn * 64 + nf * 8 + (lane & 3) * 2;
            float b0 = bias[c], b1 = bias[c + 1];
            if (r0 < M_NODES) {
                out[(size_t)r0 * DOUT + c]     = fmaxf(acc[mf][nf][0] + b0, 0.f);
                out[(size_t)r0 * DOUT + c + 1] = fmaxf(acc[mf][nf][1] + b1, 0.f);
            }
            int r1 = r0 + 8;
            if (r1 < M_NODES) {
                out[(size_t)r1 * DOUT + c]     = fmaxf(acc[mf][nf][2] + b0, 0.f);
                out[(size_t)r1 * DOUT + c + 1] = fmaxf(acc[mf][nf][3] + b1, 0.f);
            }
        }
    }
}

// ---------------------------------------------------------------------
extern "C" void kernel_launch(void* const* d_in, const int* in_sizes, int n_in,
                              void* d_out, int out_size) {
    const float* x_src = (const float*)d_in[0];
    const float* x_dst = (const float*)d_in[1];
    const int*   ei    = (const int*)d_in[2];
    const float* W     = (const float*)d_in[3];
    const float* b     = (const float*)d_in[4];
    float*       out   = (float*)d_out;
    int E = in_sizes[2] / 2;

    cudaFuncSetAttribute(k_gemm, cudaFuncAttributeMaxDynamicSharedMemorySize,
                         SMEM_BYTES);

    k_init<<<(M_NODES + 255) / 256, 256>>>(W);
    k_hist<<<(E + 255) / 256, 256>>>(ei, E);
    k_scan1<<<NBLK, 1024>>>();
    k_scan3<<<NBLK, 1024>>>();
    k_fill<<<(E + 255) / 256, 256>>>(ei, E);
    k_gather<<<(M_NODES * 32 + 255) / 256, 256>>>(x_src, x_dst);
    dim3 grid(M_PAD / BM, DOUT / BN);
    k_gemm<<<grid, NT, SMEM_BYTES>>>(b, out);
}